// round 4
// baseline (speedup 1.0000x reference)
#include <cuda_runtime.h>
#include <cuda_bf16.h>
#include <math.h>

// ---------------------------------------------------------------------------
// Problem constants: x(2,4,1024,1024), HEADS=8, D=128, ROT_DIM=64
// ---------------------------------------------------------------------------
#define BATCH   2
#define CH      4
#define BC      (BATCH*CH)        // 8
#define NB      1024              // BINS
#define NH      8                 // heads
#define HD      128               // head dim
#define BCN     (BC*NH)           // 64
#define ROT     64                // rotary dims

// Scratch (static __device__ — no allocations allowed)
__device__ float g_y [BC  * NB * NB];   // proj gemm out (pre-conv)      32MB
__device__ float g_p [BC  * NB * NB];   // conv+bias out ("ph", also V^T) 32MB
__device__ float g_q [BCN * NB * HD];   // roped Q (= K)                  32MB
__device__ float g_s [BCN * NB * NB];   // attention scores              256MB
__device__ float g_av[BCN * NB * HD];   // softmax @ V                    32MB
__device__ float g_am[BC  * NB * NB];   // merged heads (h-major)         32MB

// ---------------------------------------------------------------------------
// tf32 helpers
// ---------------------------------------------------------------------------
__device__ __forceinline__ unsigned f2tf32(float x) {
    unsigned r;
    asm("cvt.rna.tf32.f32 %0, %1;" : "=r"(r) : "f"(x));
    return r;
}

__device__ __forceinline__ void mma_tf32(float* d, const unsigned* a, const unsigned* b) {
    asm volatile(
        "mma.sync.aligned.m16n8k8.row.col.f32.tf32.tf32.f32 "
        "{%0,%1,%2,%3}, {%4,%5,%6,%7}, {%8,%9}, {%0,%1,%2,%3};"
        : "+f"(d[0]), "+f"(d[1]), "+f"(d[2]), "+f"(d[3])
        : "r"(a[0]), "r"(a[1]), "r"(a[2]), "r"(a[3]), "r"(b[0]), "r"(b[1]));
}

// ---------------------------------------------------------------------------
// Batched NT GEMM on tensor cores (tf32, fp32 accumulate):
//   C[m,n] = sum_k A[m*lda+k] * B[n*ldb+k]
// Block tile 128 x BN, BK=16, BN threads (BN/32 warps, 2 x BN/64 layout),
// warp tile 64x64 built from 4x8 m16n8k8 tiles (128B crossbar per MMA).
// Double-buffered smem (row stride 20 -> frag loads bank-conflict-free),
// register prefetch of the next global tile.
// B batch pointer = B + (batch % modB) * sB  (weights shared across b).
// ---------------------------------------------------------------------------
template<int BN>
__global__ __launch_bounds__(BN)
void gemm_tf32_nt(const float* __restrict__ A, const float* __restrict__ B,
                  float* __restrict__ C,
                  int K, int lda, int ldb, int ldc,
                  long sA, long sB, long sC, int modB)
{
    const int batch = blockIdx.z;
    A += (long)batch * sA;
    B += (long)(batch % modB) * sB;
    C += (long)batch * sC;

    __shared__ float As[2][128][20];
    __shared__ float Bs[2][BN][20];

    const int tid = threadIdx.x;
    const int bm = blockIdx.y * 128;
    const int bn = blockIdx.x * BN;

    // global loader mapping:
    //   A: 128 rows x 16 k.  BN=256: half row (2 float4) per thread.
    //                        BN=128: full row (4 float4) per thread.
    //   B: BN rows x 16 k.   one full row (4 float4) per thread.
    const int arow = (BN == 256) ? (tid >> 1) : tid;
    const int acol = (BN == 256) ? ((tid & 1) * 8) : 0;
    const int nA4  = (BN == 256) ? 2 : 4;

    const float* Ap = A + (long)(bm + arow) * lda + acol;
    const float* Bp = B + (long)(bn + tid) * ldb;

    const int wid  = tid >> 5;
    const int lane = tid & 31;
    const int wm = wid & 1;             // 0..1            (64 rows each)
    const int wn = wid >> 1;            // 0..BN/64-1      (64 cols each)
    const int g = lane >> 2;            // 0..7
    const int t = lane & 3;             // 0..3

    float acc[4][8][4];
    #pragma unroll
    for (int i = 0; i < 4; i++)
        #pragma unroll
        for (int j = 0; j < 8; j++)
            #pragma unroll
            for (int r = 0; r < 4; r++) acc[i][j][r] = 0.f;

    float4 pa[4], pb[4];

    // ---- preload tile 0 into registers, stage to smem buf 0 ----
    #pragma unroll
    for (int i = 0; i < nA4; i++) pa[i] = *(const float4*)(Ap + i * 4);
    #pragma unroll
    for (int i = 0; i < 4;   i++) pb[i] = *(const float4*)(Bp + i * 4);
    #pragma unroll
    for (int i = 0; i < nA4; i++) {
        float4 v;
        v.x = __uint_as_float(f2tf32(pa[i].x)); v.y = __uint_as_float(f2tf32(pa[i].y));
        v.z = __uint_as_float(f2tf32(pa[i].z)); v.w = __uint_as_float(f2tf32(pa[i].w));
        *(float4*)&As[0][arow][acol + i * 4] = v;
    }
    #pragma unroll
    for (int i = 0; i < 4; i++) {
        float4 v;
        v.x = __uint_as_float(f2tf32(pb[i].x)); v.y = __uint_as_float(f2tf32(pb[i].y));
        v.z = __uint_as_float(f2tf32(pb[i].z)); v.w = __uint_as_float(f2tf32(pb[i].w));
        *(float4*)&Bs[0][tid][i * 4] = v;
    }
    __syncthreads();

    const int iters = K >> 4;
    for (int it = 0; it < iters; ++it) {
        const int c = it & 1;

        // prefetch next global tile (overlaps with HMMA below)
        if (it + 1 < iters) {
            const float* ap = Ap + (it + 1) * 16;
            const float* bp = Bp + (it + 1) * 16;
            #pragma unroll
            for (int i = 0; i < nA4; i++) pa[i] = *(const float4*)(ap + i * 4);
            #pragma unroll
            for (int i = 0; i < 4;   i++) pb[i] = *(const float4*)(bp + i * 4);
        }

        // compute: 2 k-steps of m16n8k8, warp tile 64x64
        #pragma unroll
        for (int ks = 0; ks < 2; ++ks) {
            const int k0 = ks * 8;
            unsigned af[4][4], bf[8][2];
            #pragma unroll
            for (int mt = 0; mt < 4; mt++) {
                const int m = wm * 64 + mt * 16 + g;
                af[mt][0] = __float_as_uint(As[c][m    ][k0 + t]);
                af[mt][1] = __float_as_uint(As[c][m + 8][k0 + t]);
                af[mt][2] = __float_as_uint(As[c][m    ][k0 + t + 4]);
                af[mt][3] = __float_as_uint(As[c][m + 8][k0 + t + 4]);
            }
            #pragma unroll
            for (int nt = 0; nt < 8; nt++) {
                const int n = wn * 64 + nt * 8 + g;
                bf[nt][0] = __float_as_uint(Bs[c][n][k0 + t]);
                bf[nt][1] = __float_as_uint(Bs[c][n][k0 + t + 4]);
            }
            #pragma unroll
            for (int mt = 0; mt < 4; mt++)
                #pragma unroll
                for (int nt = 0; nt < 8; nt++)
                    mma_tf32(acc[mt][nt], af[mt], bf[nt]);
        }

        // stage prefetched tile into the other smem buffer
        if (it + 1 < iters) {
            const int nc = c ^ 1;
            #pragma unroll
            for (int i = 0; i < nA4; i++) {
                float4 v;
                v.x = __uint_as_float(f2tf32(pa[i].x)); v.y = __uint_as_float(f2tf32(pa[i].y));
                v.z = __uint_as_float(f2tf32(pa[i].z)); v.w = __uint_as_float(f2tf32(pa[i].w));
                *(float4*)&As[nc][arow][acol + i * 4] = v;
            }
            #pragma unroll
            for (int i = 0; i < 4; i++) {
                float4 v;
                v.x = __uint_as_float(f2tf32(pb[i].x)); v.y = __uint_as_float(f2tf32(pb[i].y));
                v.z = __uint_as_float(f2tf32(pb[i].z)); v.w = __uint_as_float(f2tf32(pb[i].w));
                *(float4*)&Bs[nc][tid][i * 4] = v;
            }
        }
        __syncthreads();
    }

    // epilogue: c0,c1 at (row, 2t), c2,c3 at (row+8, 2t)
    #pragma unroll
    for (int mt = 0; mt < 4; mt++) {
        const int row = bm + wm * 64 + mt * 16 + g;
        #pragma unroll
        for (int nt = 0; nt < 8; nt++) {
            const int col = bn + wn * 64 + nt * 8 + 2 * t;
            float2 v0 = make_float2(acc[mt][nt][0], acc[mt][nt][1]);
            float2 v1 = make_float2(acc[mt][nt][2], acc[mt][nt][3]);
            *(float2*)(C + (long)row * ldc + col)       = v0;
            *(float2*)(C + (long)(row + 8) * ldc + col) = v1;
        }
    }
}

// ---------------------------------------------------------------------------
// Depthwise conv (kernel 3, pad 1 along last axis) + bias
// ---------------------------------------------------------------------------
__global__ __launch_bounds__(256)
void conv_bias(const float* __restrict__ y, const float* __restrict__ wc,
               const float* __restrict__ bias, float* __restrict__ p)
{
    long idx = (long)blockIdx.x * blockDim.x + threadIdx.x;   // 8M elems
    if (idx >= (long)BC * NB * NB) return;
    int o = (int)(idx & (NB - 1));
    int c = (int)((idx >> 20) & 3);
    float w0 = wc[c*3+0], w1 = wc[c*3+1], w2 = wc[c*3+2];
    float mid = y[idx];
    float lft = (o > 0)      ? y[idx - 1] : 0.f;
    float rgt = (o < NB - 1) ? y[idx + 1] : 0.f;
    p[idx] = fmaf(lft, w0, fmaf(mid, w1, fmaf(rgt, w2, bias[c])));
}

// ---------------------------------------------------------------------------
// RoPE + transpose: Q[bcn][s][d] from p[bc][n*128+d][s].
// ---------------------------------------------------------------------------
__global__ __launch_bounds__(256)
void rope_build(const float* __restrict__ p, float* __restrict__ Q)
{
    long idx = (long)blockIdx.x * blockDim.x + threadIdx.x;   // 4M
    if (idx >= (long)BCN * 64 * NB) return;
    int s   = (int)(idx & (NB - 1));
    int j   = (int)((idx >> 10) & 63);
    int bcn = (int)(idx >> 16);
    int bc = bcn >> 3, n = bcn & 7;

    const float* src = p + ((long)bc * NB + n * HD) * NB + s;
    float*       dst = Q + (long)bcn * (NB * HD) + (long)s * HD;

    if (j < 32) {
        float t0 = src[(2*j + 0) * NB];
        float t1 = src[(2*j + 1) * NB];
        float invf = powf(10000.f, -(float)(2*j) / (float)ROT);
        float ang = (float)s * invf;
        float cs = cosf(ang), sn = sinf(ang);
        dst[2*j + 0] = t0 * cs - t1 * sn;
        dst[2*j + 1] = t1 * cs + t0 * sn;
    } else {
        int d = ROT + (j - 32) * 2;
        dst[d + 0] = src[(d + 0) * NB];
        dst[d + 1] = src[(d + 1) * NB];
    }
}

// ---------------------------------------------------------------------------
// Row softmax with scale (one block per row of 1024)
// ---------------------------------------------------------------------------
__global__ __launch_bounds__(256)
void softmax_rows(float* __restrict__ S, float scale)
{
    float* row = S + (long)blockIdx.x * NB;
    const int t = threadIdx.x;
    __shared__ float red[32];

    float v[4];
    float m = -1e30f;
    #pragma unroll
    for (int i = 0; i < 4; i++) {
        v[i] = row[t + i * 256] * scale;
        m = fmaxf(m, v[i]);
    }
    #pragma unroll
    for (int o = 16; o > 0; o >>= 1) m = fmaxf(m, __shfl_xor_sync(~0u, m, o));
    if ((t & 31) == 0) red[t >> 5] = m;
    __syncthreads();
    if (t < 32) {
        float x = red[t & 7];
        #pragma unroll
        for (int o = 4; o > 0; o >>= 1) x = fmaxf(x, __shfl_xor_sync(~0u, x, o));
        red[t] = x;
    }
    __syncthreads();
    m = red[0];

    float sum = 0.f;
    #pragma unroll
    for (int i = 0; i < 4; i++) { v[i] = __expf(v[i] - m); sum += v[i]; }
    #pragma unroll
    for (int o = 16; o > 0; o >>= 1) sum += __shfl_xor_sync(~0u, sum, o);
    __syncthreads();
    if ((t & 31) == 0) red[t >> 5] = sum;
    __syncthreads();
    if (t < 32) {
        float x = red[t & 7];
        #pragma unroll
        for (int o = 4; o > 0; o >>= 1) x += __shfl_xor_sync(~0u, x, o);
        red[t] = x;
    }
    __syncthreads();
    float inv = 1.f / red[0];
    #pragma unroll
    for (int i = 0; i < 4; i++) row[t + i * 256] = v[i] * inv;
}

// ---------------------------------------------------------------------------
// Merge heads: a_m[bc][n*128+d][s] = av[bcn][s][d]
// ---------------------------------------------------------------------------
__global__ __launch_bounds__(256)
void merge_heads(const float* __restrict__ av, float* __restrict__ am)
{
    __shared__ float tile[32][33];
    int bcn = blockIdx.z;
    const float* src = av + (long)bcn * (NB * HD);
    float*       dst = am + (long)bcn * (NB * HD);
    int d0 = blockIdx.x * 32, s0 = blockIdx.y * 32;
    int tx = threadIdx.x, ty = threadIdx.y;
    #pragma unroll
    for (int i = 0; i < 32; i += 8)
        tile[ty + i][tx] = src[(long)(s0 + ty + i) * HD + d0 + tx];
    __syncthreads();
    #pragma unroll
    for (int i = 0; i < 32; i += 8)
        dst[(long)(d0 + ty + i) * NB + s0 + tx] = tile[tx][ty + i];
}

// ---------------------------------------------------------------------------
// Launch
// ---------------------------------------------------------------------------
extern "C" void kernel_launch(void* const* d_in, const int* in_sizes, int n_in,
                              void* d_out, int out_size)
{
    const float* x      = (const float*)d_in[0];  // (2,4,1024,1024)
    const float* w_lin  = (const float*)d_in[1];  // (4,1024,1024)
    const float* w_conv = (const float*)d_in[2];  // (4,1,1,3)
    const float* b_conv = (const float*)d_in[3];  // (4,)
    const float* w_out  = (const float*)d_in[4];  // (4,1024,1024)
    float* out = (float*)d_out;

    float *y, *p, *q, *s, *av, *am;
    cudaGetSymbolAddress((void**)&y,  g_y);
    cudaGetSymbolAddress((void**)&p,  g_p);
    cudaGetSymbolAddress((void**)&q,  g_q);
    cudaGetSymbolAddress((void**)&s,  g_s);
    cudaGetSymbolAddress((void**)&av, g_av);
    cudaGetSymbolAddress((void**)&am, g_am);

    const long MM = (long)NB * NB;          // 1048576
    const long QS = (long)NB * HD;          // 131072

    // 1) proj GEMM: y[bc] = x[bc] @ w_lin[c]^T
    gemm_tf32_nt<256><<<dim3(4, 8, BC), 256>>>(x, w_lin, y,
        NB, NB, NB, NB, MM, MM, MM, CH);

    // 2) depthwise conv3 + bias
    conv_bias<<<(int)((BC * MM + 255) / 256), 256>>>(y, w_conv, b_conv, p);

    // 3) RoPE -> Q (== K)
    rope_build<<<(int)(((long)BCN * 64 * NB + 255) / 256), 256>>>(p, q);

    // 4) scores = Q @ Q^T   (scale folded into softmax)
    gemm_tf32_nt<256><<<dim3(4, 8, BCN), 256>>>(q, q, s,
        HD, HD, HD, NB, QS, QS, MM, BCN);

    // 5) softmax rows, scale = 1/sqrt(1024)
    softmax_rows<<<BCN * NB, 256>>>(s, 1.0f / 32.0f);

    // 6) av = P @ V   (V^T is the p slice: stride 131072 per bcn, ldb=1024)
    gemm_tf32_nt<128><<<dim3(1, 8, BCN), 128>>>(s, p, av,
        NB, NB, NB, HD, MM, QS, QS, BCN);

    // 7) merge heads (batched transpose)
    merge_heads<<<dim3(4, 32, BCN), dim3(32, 8)>>>(av, am);

    // 8) out GEMM: out[bc] = am[bc] @ w_out[c]^T
    gemm_tf32_nt<256><<<dim3(4, 8, BC), 256>>>(am, w_out, out,
        NB, NB, NB, NB, MM, MM, MM, CH);
}